// round 5
// baseline (speedup 1.0000x reference)
#include <cuda_runtime.h>
#include <cstddef>

#define THREADS 512
#define TB      64
#define DSTR    132     // duplicated-row stride (floats) per unit: 128 data + 4 pad
#define T_ENC   100
#define T_DEC   60

typedef unsigned long long ull;

// ---------------- prepped weights ----------------
// Per layer, pass-major: [pass q (2)][k (Kxp+128)][256 cols], col = owner*4 + chunkpair*2 + parity.
// My chunk order [i,g,f,o]: pass0=(i,g), pass1=(f,o). Original torch order [i,f,g,o].
__device__ float g_w_enc0[2 * 144 * 256];
__device__ float g_w_enc1[2 * 256 * 256];
__device__ float g_w_dec0[2 * 144 * 256];
__device__ float g_w_dec1[2 * 256 * 256];
__device__ float g_bias[4 * 512];

__device__ __forceinline__ int permchunk(int m) {   // my chunk -> original chunk
    return (m == 1) ? 2 : ((m == 2) ? 1 : m);
}

__device__ void fill_layer(float* dst, const float* Wih, const float* Whh,
                           int Kx, int Kxp, int tid, int nth) {
    int Ktot = Kxp + 128;
    int total = 2 * Ktot * 256;
    for (int idx = tid; idx < total; idx += nth) {
        int q   = idx / (Ktot * 256);
        int rem = idx - q * (Ktot * 256);
        int k   = rem >> 8;
        int col = rem & 255;
        int o = col >> 2, cp = (col >> 1) & 1, par = col & 1;
        int oc  = permchunk(q * 2 + cp);
        int row = oc * 128 + 2 * o + par;
        float v;
        if (k < Kxp) v = (k < Kx) ? Wih[row * Kx + k] : 0.0f;
        else         v = Whh[row * 128 + (k - Kxp)];
        dst[idx] = v;
    }
}

__device__ void fill_bias(float* dst, const float* bih, const float* bhh,
                          int tid, int nth) {
    for (int c = tid; c < 512; c += nth) {
        int q = c >> 8, col = c & 255;
        int o = col >> 2, cp = (col >> 1) & 1, par = col & 1;
        int oc  = permchunk(q * 2 + cp);
        int row = oc * 128 + 2 * o + par;
        dst[c] = bih[row] + bhh[row];
    }
}

__global__ void prep_kernel(
    const float* eWih0, const float* eWhh0, const float* ebih0, const float* ebhh0,
    const float* eWih1, const float* eWhh1, const float* ebih1, const float* ebhh1,
    const float* dWih0, const float* dWhh0, const float* dbih0, const float* dbhh0,
    const float* dWih1, const float* dWhh1, const float* dbih1, const float* dbhh1)
{
    int tid = blockIdx.x * blockDim.x + threadIdx.x;
    int nth = gridDim.x * blockDim.x;
    fill_layer(g_w_enc0, eWih0, eWhh0, 16,  16,  tid, nth);
    fill_layer(g_w_enc1, eWih1, eWhh1, 128, 128, tid, nth);
    fill_layer(g_w_dec0, dWih0, dWhh0, 2,   16,  tid, nth);
    fill_layer(g_w_dec1, dWih1, dWhh1, 128, 128, tid, nth);
    fill_bias(g_bias + 0 * 512, ebih0, ebhh0, tid, nth);
    fill_bias(g_bias + 1 * 512, ebih1, ebhh1, tid, nth);
    fill_bias(g_bias + 2 * 512, dbih0, dbhh0, tid, nth);
    fill_bias(g_bias + 3 * 512, dbih1, dbhh1, tid, nth);
}

// ---------------- packed f32x2 helpers ----------------
__device__ __forceinline__ void fma2(ull& d, ull a, ull b) {
    asm("fma.rn.f32x2 %0, %1, %2, %0;" : "+l"(d) : "l"(a), "l"(b));
}
__device__ __forceinline__ ull pack2(float lo, float hi) {
    ull r;
    asm("mov.b64 %0, {%1, %2};" : "=l"(r)
        : "r"(__float_as_uint(lo)), "r"(__float_as_uint(hi)));
    return r;
}
__device__ __forceinline__ float2 unpack2(ull v) {
    unsigned lo, hi;
    asm("mov.b64 {%0, %1}, %2;" : "=r"(lo), "=r"(hi) : "l"(v));
    return make_float2(__uint_as_float(lo), __uint_as_float(hi));
}

// ---------------- fast activations (safe fp32, ~1e-7) ----------------
__device__ __forceinline__ float fsig(float v) {
    return __fdividef(1.0f, 1.0f + __expf(-v));
}
__device__ __forceinline__ float ftanh(float v) {
    float a = fabsf(v);
    float e = __expf(-2.0f * a);
    float t = __fdividef(1.0f - e, 1.0f + e);
    return (v < 0.0f) ? -t : t;
}

// ---------------- cp.async weight staging (one 16x256 tile = 16KB) ----------------
__device__ __forceinline__ void stage_tile(unsigned wtb, int buf, const float* src, int tid) {
    unsigned d = wtb + buf * 16384 + tid * 16;
    const float* s = src + tid * 4;
    asm volatile("cp.async.cg.shared.global [%0], [%1], 16;\n" :: "r"(d), "l"(s));
    asm volatile("cp.async.cg.shared.global [%0], [%1], 16;\n" :: "r"(d + 8192), "l"(s + 2048));
    asm volatile("cp.async.commit_group;\n");
}
__device__ __forceinline__ void cp_wait1() { asm volatile("cp.async.wait_group 1;\n"); }
__device__ __forceinline__ void cp_wait0() { asm volatile("cp.async.wait_group 0;\n"); }

// ---------------- one LSTM layer step (this CTA's 64 rows) ----------------
// Tiles 0..akt-1 read srcA (dup layout), tiles akt..nkt-1 read hT (old, dup). Writes hT (dup).
__device__ __forceinline__ void run_layer(
    const float* __restrict__ Wg, const float* __restrict__ biasL,
    int nkt, int akt,
    const float* __restrict__ srcA, float* __restrict__ hT,
    const float* __restrict__ wt, unsigned wtb, float2 (&cst)[8],
    int tr2, int o, int tid)
{
    float a0[8], a1[8];     // pass0 result: sigmoid(i)*tanh(g), units 2o / 2o+1
#pragma unroll 1
    for (int q = 0; q < 2; q++) {
        const float* Wp = Wg + (size_t)q * nkt * 4096;
        __syncthreads();                      // prev users of wt done; state writes visible
        stage_tile(wtb, 0, Wp, tid);
        stage_tile(wtb, 1, Wp + 4096, tid);

        float4 bv = *(const float4*)(biasL + q * 256 + o * 4);
        ull acc0[8], acc1[8];
        ull b01 = pack2(bv.x, bv.y), b23 = pack2(bv.z, bv.w);
#pragma unroll
        for (int i = 0; i < 8; i++) { acc0[i] = b01; acc1[i] = b23; }

#pragma unroll 1
        for (int kt = 0; kt < nkt; kt++) {
            if (kt + 1 < nkt) cp_wait1(); else cp_wait0();
            __syncthreads();                  // tile kt visible; buf[(kt+2)%3] free
            if (kt + 2 < nkt) stage_tile(wtb, (kt + 2) % 3, Wp + (size_t)(kt + 2) * 4096, tid);

            const float* z = (kt < akt) ? (srcA + kt * 16 * DSTR + tr2)
                                        : (hT + (kt - akt) * 16 * DSTR + tr2);
            const float* wS = wt + (kt % 3) * 4096 + o * 4;
#pragma unroll
            for (int k2 = 0; k2 < 16; k2++) {
                ulonglong2 wu = *(const ulonglong2*)(wS + k2 * 256);
                const float* zz = z + k2 * DSTR;
                ulonglong2 hA = *(const ulonglong2*)(zz);        // rows tr..tr+1 (dup lanes)
                ulonglong2 hB = *(const ulonglong2*)(zz + 4);
                ulonglong2 hC = *(const ulonglong2*)(zz + 8);
                ulonglong2 hD = *(const ulonglong2*)(zz + 12);
                fma2(acc0[0], hA.x, wu.x); fma2(acc1[0], hA.x, wu.y);
                fma2(acc0[1], hA.y, wu.x); fma2(acc1[1], hA.y, wu.y);
                fma2(acc0[2], hB.x, wu.x); fma2(acc1[2], hB.x, wu.y);
                fma2(acc0[3], hB.y, wu.x); fma2(acc1[3], hB.y, wu.y);
                fma2(acc0[4], hC.x, wu.x); fma2(acc1[4], hC.x, wu.y);
                fma2(acc0[5], hC.y, wu.x); fma2(acc1[5], hC.y, wu.y);
                fma2(acc0[6], hD.x, wu.x); fma2(acc1[6], hD.x, wu.y);
                fma2(acc0[7], hD.y, wu.x); fma2(acc1[7], hD.y, wu.y);
            }
        }

        if (q == 0) {
#pragma unroll
            for (int i = 0; i < 8; i++) {
                float2 iv = unpack2(acc0[i]);   // gate i, units (2o, 2o+1), row tr+i
                float2 gv = unpack2(acc1[i]);   // gate g
                a0[i] = fsig(iv.x) * ftanh(gv.x);
                a1[i] = fsig(iv.y) * ftanh(gv.y);
            }
        } else {
            __syncthreads();                  // all threads done reading old hT
            float h0v[8], h1v[8];
#pragma unroll
            for (int i = 0; i < 8; i++) {
                float2 fv = unpack2(acc0[i]);   // gate f
                float2 ov = unpack2(acc1[i]);   // gate o
                float cx = fmaf(fsig(fv.x), cst[i].x, a0[i]);
                float cy = fmaf(fsig(fv.y), cst[i].y, a1[i]);
                cst[i] = make_float2(cx, cy);
                h0v[i] = fsig(ov.x) * ftanh(cx);
                h1v[i] = fsig(ov.y) * ftanh(cy);
            }
            float* p0 = hT + (2 * o)     * DSTR + tr2;   // unit 2o, duplicated rows
            float* p1 = hT + (2 * o + 1) * DSTR + tr2;   // unit 2o+1
#pragma unroll
            for (int j = 0; j < 4; j++) {
                *(float4*)(p0 + 4 * j) = make_float4(h0v[2*j], h0v[2*j], h0v[2*j+1], h0v[2*j+1]);
                *(float4*)(p1 + 4 * j) = make_float4(h1v[2*j], h1v[2*j], h1v[2*j+1], h1v[2*j+1]);
            }
        }
    }
}

// ---------------- smem layout (float offsets) ----------------
#define SM_HT0  0               // 128*DSTR = 16896
#define SM_HT1  16896           // 16896
#define SM_XT   33792           // 16*DSTR = 2112
#define SM_BIAS 35904           // 2048
#define SM_FC   37952           // 272
#define SM_WT   38224           // 3*4096 = 12288 (16B aligned)
#define SM_TOT  50512           // 202,048 bytes

// ---------------- main persistent kernel: 128 CTAs x 64 rows ----------------
__global__ __launch_bounds__(THREADS, 1)
void TrajectoryPredictor_12807592476996_kernel(
    const float* __restrict__ x, const float* __restrict__ fcW,
    const float* __restrict__ fcb, float* __restrict__ out)
{
    extern __shared__ float sm[];
    float* hT0  = sm + SM_HT0;
    float* hT1  = sm + SM_HT1;
    float* xT   = sm + SM_XT;
    float* bias = sm + SM_BIAS;
    float* fcs  = sm + SM_FC;
    float* wt   = sm + SM_WT;
    const unsigned wtb = (unsigned)__cvta_generic_to_shared(wt);

    const int tid = threadIdx.x;
    const int r0  = blockIdx.x * TB;

    for (int i = tid; i < 2 * 16896; i += THREADS) hT0[i] = 0.0f;
    for (int i = tid; i < 2048; i += THREADS) bias[i] = g_bias[i];
    if (tid < 256) fcs[tid] = fcW[tid];
    if (tid < 2)   fcs[256 + tid] = fcb[tid];

    float2 c0[8], c1[8];
#pragma unroll
    for (int i = 0; i < 8; i++) { c0[i] = make_float2(0.f, 0.f); c1[i] = make_float2(0.f, 0.f); }

    // LANE REMAP (round-4 change): within a warp, 4 owners x 8 rowgroups.
    // w-load: 4 unique 16B chunks (8-way broadcast) -> ~1 crossbar phase.
    // h-load: 8 unique addresses (4-way broadcast)  -> 1 phase per LDS.128.
    const int wrp  = tid >> 5, lane = tid & 31;
    const int o    = wrp * 4 + (lane & 3);      // pair-column owner (units 2o, 2o+1)
    const int tr2  = (lane >> 2) * 16;          // duplicated-row offset (8 rows -> 16 floats)

#pragma unroll 1
    for (int t = 0; t < T_ENC + T_DEC; t++) {
        if (t < T_ENC) {
            for (int u = tid; u < 16 * TB; u += THREADS) {
                int k = u & 15, r = u >> 4;
                float v = x[(size_t)(r0 + r) * 1600 + t * 16 + k];
                *(float2*)(xT + k * DSTR + 2 * r) = make_float2(v, v);
            }
        } else if (t == T_ENC) {
            for (int u = tid; u < 16 * TB; u += THREADS) {
                int k = u & 15, r = u >> 4;
                float v = (k < 2) ? x[(size_t)(r0 + r) * 1600 + (T_ENC - 1) * 16 + k] : 0.0f;
                *(float2*)(xT + k * DSTR + 2 * r) = make_float2(v, v);
            }
        }
        const bool enc = (t < T_ENC);
        const float* Wa = enc ? g_w_enc0 : g_w_dec0;
        const float* Wb = enc ? g_w_enc1 : g_w_dec1;
        const float* Ba = bias + (enc ? 0 : 2 * 512);
        const float* Bb = bias + (enc ? 512 : 3 * 512);

        run_layer(Wa, Ba, 9, 1, xT, hT0, wt, wtb, c0, tr2, o, tid);    // layer 0
        run_layer(Wb, Bb, 16, 8, hT0, hT1, wt, wtb, c1, tr2, o, tid);  // layer 1

        if (!enc) {
            __syncthreads();                  // hT1 writes visible to fc readers
            if (tid < 128) {
                int r = tid >> 1, oo = tid & 1;
                const float* wrow = fcs + oo * 128;
                float s0 = 0.f, s1 = 0.f;
#pragma unroll
                for (int j = 0; j < 128; j += 2) {
                    s0 = fmaf(hT1[j * DSTR + 2 * r],       wrow[j],     s0);
                    s1 = fmaf(hT1[(j + 1) * DSTR + 2 * r], wrow[j + 1], s1);
                }
                float s = s0 + s1 + fcs[256 + oo];
                out[(size_t)(r0 + r) * (T_DEC * 2) + (t - T_ENC) * 2 + oo] = s;
                *(float2*)(xT + oo * DSTR + 2 * r) = make_float2(s, s);   // feedback
            }
            // next run_layer's entry barrier orders xT writes vs reads
        }
    }
}

// ---------------- launch ----------------
extern "C" void kernel_launch(void* const* d_in, const int* in_sizes, int n_in,
                              void* d_out, int out_size)
{
    (void)in_sizes; (void)n_in; (void)out_size;
    const float* x = (const float*)d_in[0];
    // d_in[1] = target_len (fixed 60)
    const float* eWih0 = (const float*)d_in[2];
    const float* eWhh0 = (const float*)d_in[3];
    const float* ebih0 = (const float*)d_in[4];
    const float* ebhh0 = (const float*)d_in[5];
    const float* eWih1 = (const float*)d_in[6];
    const float* eWhh1 = (const float*)d_in[7];
    const float* ebih1 = (const float*)d_in[8];
    const float* ebhh1 = (const float*)d_in[9];
    const float* dWih0 = (const float*)d_in[10];
    const float* dWhh0 = (const float*)d_in[11];
    const float* dbih0 = (const float*)d_in[12];
    const float* dbhh0 = (const float*)d_in[13];
    const float* dWih1 = (const float*)d_in[14];
    const float* dWhh1 = (const float*)d_in[15];
    const float* dbih1 = (const float*)d_in[16];
    const float* dbhh1 = (const float*)d_in[17];
    const float* fcW   = (const float*)d_in[18];
    const float* fcb   = (const float*)d_in[19];

    prep_kernel<<<256, 256>>>(eWih0, eWhh0, ebih0, ebhh0,
                              eWih1, eWhh1, ebih1, ebhh1,
                              dWih0, dWhh0, dbih0, dbhh0,
                              dWih1, dWhh1, dbih1, dbhh1);

    const size_t smem = (size_t)SM_TOT * sizeof(float);
    cudaFuncSetAttribute(TrajectoryPredictor_12807592476996_kernel,
                         cudaFuncAttributeMaxDynamicSharedMemorySize, (int)smem);
    TrajectoryPredictor_12807592476996_kernel<<<128, THREADS, smem>>>(
        x, fcW, fcb, (float*)d_out);
}

// round 6
// speedup vs baseline: 1.4239x; 1.4239x over previous
#include <cuda_runtime.h>
#include <cstddef>

#define THREADS 512
#define TB      64
#define HSTR    68      // unit-row stride (floats): 64 rows + swizzle padding
#define T_ENC   100
#define T_DEC   60

typedef unsigned long long ull;

// ---------------- prepped weights (DUPLICATED columns) ----------------
// Per layer, pass-major: [pass q (2)][k (Kxp+128)][512], where the 512 = 256 cols
// each duplicated in adjacent lanes: dup[2c]=dup[2c+1]=W[c]. col c = o*4+cp*2+par.
// Chunk order [i,g,f,o]: pass0=(i,g), pass1=(f,o). Torch order [i,f,g,o].
__device__ float g_w_enc0[2 * 144 * 512];
__device__ float g_w_enc1[2 * 256 * 512];
__device__ float g_w_dec0[2 * 144 * 512];
__device__ float g_w_dec1[2 * 256 * 512];
__device__ float g_bias[4 * 512];

__device__ __forceinline__ int permchunk(int m) {   // my chunk -> original chunk
    return (m == 1) ? 2 : ((m == 2) ? 1 : m);
}

__device__ void fill_layer_dup(float* dst, const float* Wih, const float* Whh,
                               int Kx, int Kxp, int tid, int nth) {
    int Ktot = Kxp + 128;
    int total = 2 * Ktot * 512;
    for (int idx = tid; idx < total; idx += nth) {
        int q   = idx / (Ktot * 512);
        int rem = idx - q * (Ktot * 512);
        int k   = rem >> 9;
        int c   = (rem & 511) >> 1;             // actual column (dup pairs)
        int o = c >> 2, cp = (c >> 1) & 1, par = c & 1;
        int oc  = permchunk(q * 2 + cp);
        int row = oc * 128 + 2 * o + par;
        float v;
        if (k < Kxp) v = (k < Kx) ? Wih[row * Kx + k] : 0.0f;
        else         v = Whh[row * 128 + (k - Kxp)];
        dst[idx] = v;
    }
}

__device__ void fill_bias(float* dst, const float* bih, const float* bhh,
                          int tid, int nth) {
    for (int c = tid; c < 512; c += nth) {
        int q = c >> 8, col = c & 255;
        int o = col >> 2, cp = (col >> 1) & 1, par = col & 1;
        int oc  = permchunk(q * 2 + cp);
        int row = oc * 128 + 2 * o + par;
        dst[c] = bih[row] + bhh[row];
    }
}

__global__ void prep_kernel(
    const float* eWih0, const float* eWhh0, const float* ebih0, const float* ebhh0,
    const float* eWih1, const float* eWhh1, const float* ebih1, const float* ebhh1,
    const float* dWih0, const float* dWhh0, const float* dbih0, const float* dbhh0,
    const float* dWih1, const float* dWhh1, const float* dbih1, const float* dbhh1)
{
    int tid = blockIdx.x * blockDim.x + threadIdx.x;
    int nth = gridDim.x * blockDim.x;
    fill_layer_dup(g_w_enc0, eWih0, eWhh0, 16,  16,  tid, nth);
    fill_layer_dup(g_w_enc1, eWih1, eWhh1, 128, 128, tid, nth);
    fill_layer_dup(g_w_dec0, dWih0, dWhh0, 2,   16,  tid, nth);
    fill_layer_dup(g_w_dec1, dWih1, dWhh1, 128, 128, tid, nth);
    fill_bias(g_bias + 0 * 512, ebih0, ebhh0, tid, nth);
    fill_bias(g_bias + 1 * 512, ebih1, ebhh1, tid, nth);
    fill_bias(g_bias + 2 * 512, dbih0, dbhh0, tid, nth);
    fill_bias(g_bias + 3 * 512, dbih1, dbhh1, tid, nth);
}

// ---------------- packed f32x2 helpers ----------------
__device__ __forceinline__ void fma2(ull& d, ull a, ull b) {
    asm("fma.rn.f32x2 %0, %1, %2, %0;" : "+l"(d) : "l"(a), "l"(b));
}
__device__ __forceinline__ ull pack2(float lo, float hi) {
    ull r;
    asm("mov.b64 %0, {%1, %2};" : "=l"(r)
        : "r"(__float_as_uint(lo)), "r"(__float_as_uint(hi)));
    return r;
}
__device__ __forceinline__ float2 unpack2(ull v) {
    unsigned lo, hi;
    asm("mov.b64 {%0, %1}, %2;" : "=r"(lo), "=r"(hi) : "l"(v));
    return make_float2(__uint_as_float(lo), __uint_as_float(hi));
}

// ---------------- safe fp32 activations ----------------
__device__ __forceinline__ float fsig(float v) {
    return __fdividef(1.0f, 1.0f + __expf(-v));
}
__device__ __forceinline__ float ftanh(float v) {
    float a = fabsf(v);
    float e = __expf(-2.0f * a);
    float t = __fdividef(1.0f - e, 1.0f + e);
    return (v < 0.0f) ? -t : t;
}

// ---------------- cp.async staging (one dup tile = 16k x 512 = 32KB) ----------------
__device__ __forceinline__ void stage_tile(unsigned wtb, int buf, const float* src, int tid) {
    unsigned d = wtb + buf * 32768 + tid * 16;
    const float* s = src + tid * 4;
#pragma unroll
    for (int i = 0; i < 4; i++)
        asm volatile("cp.async.cg.shared.global [%0], [%1], 16;\n"
                     :: "r"(d + i * 8192), "l"(s + i * 2048));
    asm volatile("cp.async.commit_group;\n");
}
__device__ __forceinline__ void cp_wait1() { asm volatile("cp.async.wait_group 1;\n"); }
__device__ __forceinline__ void cp_wait0() { asm volatile("cp.async.wait_group 0;\n"); }

// ---------------- one LSTM layer step (this CTA's 64 rows) ----------------
// Tiles 0..akt-1 read srcA, tiles akt..nkt-1 read hT (old). Writes hT.
// States are [unit][row] with HSTR stride, rows placed at rowoff swizzle.
__device__ __forceinline__ void run_layer(
    const float* __restrict__ Wg, const float* __restrict__ biasL,
    int nkt, int akt,
    const float* __restrict__ srcA, float* __restrict__ hT,
    const float* __restrict__ wt, unsigned wtb, float2 (&cst)[8],
    int rowbase, int o, int tid)
{
    float a0[8], a1[8];     // pass0: sigmoid(i)*tanh(g) for units 2o / 2o+1, 8 rows
#pragma unroll 1
    for (int q = 0; q < 2; q++) {
        const float* Wp = Wg + (size_t)q * nkt * 8192;
        __syncthreads();                      // prev users of wt done; state writes visible
        stage_tile(wtb, 0, Wp, tid);
        stage_tile(wtb, 1, Wp + 8192, tid);

        float4 bv = *(const float4*)(biasL + q * 256 + o * 4);
        ull acc[16];                          // [c(4)][rowpair(4)]
        {
            ull b0 = pack2(bv.x, bv.x), b1 = pack2(bv.y, bv.y);
            ull b2 = pack2(bv.z, bv.z), b3 = pack2(bv.w, bv.w);
#pragma unroll
            for (int rp = 0; rp < 4; rp++) {
                acc[rp] = b0; acc[4 + rp] = b1; acc[8 + rp] = b2; acc[12 + rp] = b3;
            }
        }

#pragma unroll 1
        for (int kt = 0; kt < nkt; kt++) {
            if (kt + 1 < nkt) cp_wait1(); else cp_wait0();
            __syncthreads();                  // tile kt visible; buf[(kt+2)%3] free
            if (kt + 2 < nkt) stage_tile(wtb, (kt + 2) % 3, Wp + (size_t)(kt + 2) * 8192, tid);

            const float* z = (kt < akt) ? (srcA + kt * 16 * HSTR + rowbase)
                                        : (hT + (kt - akt) * 16 * HSTR + rowbase);
            const float* wS = wt + (kt % 3) * 8192 + o * 8;
#pragma unroll
            for (int k2 = 0; k2 < 16; k2++) {
                ulonglong2 wA = *(const ulonglong2*)(wS + k2 * 512);      // (wc0,wc0),(wc1,wc1)
                ulonglong2 wB = *(const ulonglong2*)(wS + k2 * 512 + 4);  // (wc2,wc2),(wc3,wc3)
                const float* zz = z + k2 * HSTR;
                ulonglong2 ha = *(const ulonglong2*)(zz);        // rows (r0,r1),(r2,r3)
                ulonglong2 hb = *(const ulonglong2*)(zz + 4);    // rows (r4,r5),(r6,r7)
                fma2(acc[0],  ha.x, wA.x); fma2(acc[1],  ha.y, wA.x);
                fma2(acc[2],  hb.x, wA.x); fma2(acc[3],  hb.y, wA.x);
                fma2(acc[4],  ha.x, wA.y); fma2(acc[5],  ha.y, wA.y);
                fma2(acc[6],  hb.x, wA.y); fma2(acc[7],  hb.y, wA.y);
                fma2(acc[8],  ha.x, wB.x); fma2(acc[9],  ha.y, wB.x);
                fma2(acc[10], hb.x, wB.x); fma2(acc[11], hb.y, wB.x);
                fma2(acc[12], ha.x, wB.y); fma2(acc[13], ha.y, wB.y);
                fma2(acc[14], hb.x, wB.y); fma2(acc[15], hb.y, wB.y);
            }
        }

        if (q == 0) {
            // c0,c1 = gate i (units 2o, 2o+1); c2,c3 = gate g
#pragma unroll
            for (int rp = 0; rp < 4; rp++) {
                float2 i0 = unpack2(acc[rp]),      i1 = unpack2(acc[4 + rp]);
                float2 g0 = unpack2(acc[8 + rp]),  g1 = unpack2(acc[12 + rp]);
                a0[2*rp]   = fsig(i0.x) * ftanh(g0.x);
                a0[2*rp+1] = fsig(i0.y) * ftanh(g0.y);
                a1[2*rp]   = fsig(i1.x) * ftanh(g1.x);
                a1[2*rp+1] = fsig(i1.y) * ftanh(g1.y);
            }
        } else {
            __syncthreads();                  // all threads done reading old hT
            float h0v[8], h1v[8];
#pragma unroll
            for (int rp = 0; rp < 4; rp++) {
                float2 f0 = unpack2(acc[rp]),      f1 = unpack2(acc[4 + rp]);
                float2 o0 = unpack2(acc[8 + rp]),  o1 = unpack2(acc[12 + rp]);
                int i = 2 * rp;
                float cx0 = fmaf(fsig(f0.x), cst[i].x,     a0[i]);
                float cx1 = fmaf(fsig(f0.y), cst[i + 1].x, a0[i + 1]);
                float cy0 = fmaf(fsig(f1.x), cst[i].y,     a1[i]);
                float cy1 = fmaf(fsig(f1.y), cst[i + 1].y, a1[i + 1]);
                cst[i]     = make_float2(cx0, cy0);
                cst[i + 1] = make_float2(cx1, cy1);
                h0v[i]     = fsig(o0.x) * ftanh(cx0);
                h0v[i + 1] = fsig(o0.y) * ftanh(cx1);
                h1v[i]     = fsig(o1.x) * ftanh(cy0);
                h1v[i + 1] = fsig(o1.y) * ftanh(cy1);
            }
            float* p0 = hT + (2 * o)     * HSTR + rowbase;
            float* p1 = hT + (2 * o + 1) * HSTR + rowbase;
            *(float4*)(p0)     = make_float4(h0v[0], h0v[1], h0v[2], h0v[3]);
            *(float4*)(p0 + 4) = make_float4(h0v[4], h0v[5], h0v[6], h0v[7]);
            *(float4*)(p1)     = make_float4(h1v[0], h1v[1], h1v[2], h1v[3]);
            *(float4*)(p1 + 4) = make_float4(h1v[4], h1v[5], h1v[6], h1v[7]);
        }
    }
}

// row placement swizzle: row r (0..63) lives at offset r + 4*(r>>5)
__device__ __forceinline__ int rowoff(int r) { return r + ((r >> 5) << 2); }

// ---------------- smem layout (float offsets) ----------------
#define SM_HT0  0               // 128*HSTR = 8704
#define SM_HT1  8704
#define SM_XT   17408           // 16*HSTR = 1088
#define SM_BIAS 18496           // 2048
#define SM_FC   20544           // 272
#define SM_WT   20816           // 3*8192 = 24576 (16B aligned)
#define SM_TOT  45392           // 181,568 bytes

// ---------------- main persistent kernel: 128 CTAs x 64 rows ----------------
__global__ __launch_bounds__(THREADS, 1)
void TrajectoryPredictor_12807592476996_kernel(
    const float* __restrict__ x, const float* __restrict__ fcW,
    const float* __restrict__ fcb, float* __restrict__ out)
{
    extern __shared__ float sm[];
    float* hT0  = sm + SM_HT0;
    float* hT1  = sm + SM_HT1;
    float* xT   = sm + SM_XT;
    float* bias = sm + SM_BIAS;
    float* fcs  = sm + SM_FC;
    float* wt   = sm + SM_WT;
    const unsigned wtb = (unsigned)__cvta_generic_to_shared(wt);

    const int tid = threadIdx.x;
    const int r0  = blockIdx.x * TB;

    for (int i = tid; i < 2 * 8704; i += THREADS) hT0[i] = 0.0f;
    for (int i = tid; i < 2048; i += THREADS) bias[i] = g_bias[i];
    if (tid < 256) fcs[tid] = fcW[tid];
    if (tid < 2)   fcs[256 + tid] = fcb[tid];

    float2 c0[8], c1[8];
#pragma unroll
    for (int i = 0; i < 8; i++) { c0[i] = make_float2(0.f, 0.f); c1[i] = make_float2(0.f, 0.f); }

    // lane map: 4 owners x 8 rowgroups per warp.
    // h-load: 8 unique conflict-free addresses (banks {0,8,16,24,4,12,20,28}), 4-way bcast.
    // w-load: 4 unique 16B chunks, contiguous 64B, 8-way bcast.
    const int wrp = tid >> 5, lane = tid & 31;
    const int o   = wrp * 4 + (lane & 3);               // pair-column owner (units 2o,2o+1)
    const int rg  = lane >> 2;                          // rowgroup (rows rg*8..rg*8+7)
    const int rowbase = rg * 8 + ((rg >> 2) << 2);      // conflict-free swizzle

#pragma unroll 1
    for (int t = 0; t < T_ENC + T_DEC; t++) {
        if (t < T_ENC) {
            for (int u = tid; u < 16 * TB; u += THREADS) {
                int k = u & 15, r = u >> 4;
                xT[k * HSTR + rowoff(r)] = x[(size_t)(r0 + r) * 1600 + t * 16 + k];
            }
        } else if (t == T_ENC) {
            for (int u = tid; u < 16 * TB; u += THREADS) {
                int k = u & 15, r = u >> 4;
                xT[k * HSTR + rowoff(r)] = (k < 2)
                    ? x[(size_t)(r0 + r) * 1600 + (T_ENC - 1) * 16 + k] : 0.0f;
            }
        }
        const bool enc = (t < T_ENC);
        const float* Wa = enc ? g_w_enc0 : g_w_dec0;
        const float* Wb = enc ? g_w_enc1 : g_w_dec1;
        const float* Ba = bias + (enc ? 0 : 2 * 512);
        const float* Bb = bias + (enc ? 512 : 3 * 512);

        run_layer(Wa, Ba, 9, 1, xT, hT0, wt, wtb, c0, rowbase, o, tid);    // layer 0
        run_layer(Wb, Bb, 16, 8, hT0, hT1, wt, wtb, c1, rowbase, o, tid);  // layer 1

        if (!enc) {
            __syncthreads();                  // hT1 writes visible to fc readers
            if (tid < 128) {
                int r = tid >> 1, oo = tid & 1;
                int ro = rowoff(r);
                const float* wrow = fcs + oo * 128;
                float s0 = 0.f, s1 = 0.f;
#pragma unroll
                for (int j = 0; j < 128; j += 2) {
                    s0 = fmaf(hT1[j * HSTR + ro],       wrow[j],     s0);
                    s1 = fmaf(hT1[(j + 1) * HSTR + ro], wrow[j + 1], s1);
                }
                float s = s0 + s1 + fcs[256 + oo];
                out[(size_t)(r0 + r) * (T_DEC * 2) + (t - T_ENC) * 2 + oo] = s;
                xT[oo * HSTR + ro] = s;       // feedback as next decoder input
            }
            // next run_layer's entry barrier orders xT writes vs reads
        }
    }
}

// ---------------- launch ----------------
extern "C" void kernel_launch(void* const* d_in, const int* in_sizes, int n_in,
                              void* d_out, int out_size)
{
    (void)in_sizes; (void)n_in; (void)out_size;
    const float* x = (const float*)d_in[0];
    // d_in[1] = target_len (fixed 60)
    const float* eWih0 = (const float*)d_in[2];
    const float* eWhh0 = (const float*)d_in[3];
    const float* ebih0 = (const float*)d_in[4];
    const float* ebhh0 = (const float*)d_in[5];
    const float* eWih1 = (const float*)d_in[6];
    const float* eWhh1 = (const float*)d_in[7];
    const float* ebih1 = (const float*)d_in[8];
    const float* ebhh1 = (const float*)d_in[9];
    const float* dWih0 = (const float*)d_in[10];
    const float* dWhh0 = (const float*)d_in[11];
    const float* dbih0 = (const float*)d_in[12];
    const float* dbhh0 = (const float*)d_in[13];
    const float* dWih1 = (const float*)d_in[14];
    const float* dWhh1 = (const float*)d_in[15];
    const float* dbih1 = (const float*)d_in[16];
    const float* dbhh1 = (const float*)d_in[17];
    const float* fcW   = (const float*)d_in[18];
    const float* fcb   = (const float*)d_in[19];

    prep_kernel<<<256, 256>>>(eWih0, eWhh0, ebih0, ebhh0,
                              eWih1, eWhh1, ebih1, ebhh1,
                              dWih0, dWhh0, dbih0, dbhh0,
                              dWih1, dWhh1, dbih1, dbhh1);

    const size_t smem = (size_t)SM_TOT * sizeof(float);
    cudaFuncSetAttribute(TrajectoryPredictor_12807592476996_kernel,
                         cudaFuncAttributeMaxDynamicSharedMemorySize, (int)smem);
    TrajectoryPredictor_12807592476996_kernel<<<128, THREADS, smem>>>(
        x, fcW, fcb, (float*)d_out);
}